// round 14
// baseline (speedup 1.0000x reference)
#include <cuda_runtime.h>
#include <cuda_fp16.h>
#include <cstdint>

#define Nn    10000
#define Mrows 160000
#define NTILE 2500          // 64-row tiles
#define GRID  148

__device__ __forceinline__ uint32_t smem_u32(const void* p) {
    uint32_t a;
    asm("{ .reg .u64 t; cvta.to.shared.u64 t, %1; cvt.u32.u64 %0, t; }" : "=r"(a) : "l"(p));
    return a;
}

// Wv pre-converted to fp16, [k][c] (c = 0..255)
__device__ __half g_Bh[(size_t)256 * 256];

// ======================= fused GEMM + LayerNorm (warp-specialized) ==========
// out = LN_perhead(x @ Wv), permuted row write. Retention weight w cancels
// through LN (w>0, eps/w^2 ~1e-6 rel). Single-pass fp16 == exact GEMM against
// fp16-quantized x and Wv; rel err ~2.8e-4 (gate 1e-3).
// 148 persistent CTAs x 256 thr: warps 0-3 consume (64x64 warp tile, one full
// head each -> no B-fragment duplication), warps 4-7 produce (cp.async stage
// -> fp16 convert -> STS). 1 consumer + 1 producer per SMSP.
#define SM_B   0
#define SM_A   131072        // 2 x 32768
#define SM_S   196608        // 2 x 16384
#define SM_TOT 229376

#define BAR_FULL0  1
#define BAR_EMPTY0 3
#define BCNT 256

__device__ __forceinline__ void bar_sync(int id) {
    asm volatile("bar.sync %0, %1;" :: "r"(id), "r"(BCNT) : "memory");
}
__device__ __forceinline__ void bar_arrive(int id) {
    asm volatile("bar.arrive %0, %1;" :: "r"(id), "r"(BCNT) : "memory");
}

__device__ __forceinline__ void ldsm_x4(uint32_t* r, uint32_t addr) {
    asm volatile("ldmatrix.sync.aligned.m8n8.x4.shared.b16 {%0,%1,%2,%3}, [%4];"
                 : "=r"(r[0]), "=r"(r[1]), "=r"(r[2]), "=r"(r[3]) : "r"(addr));
}
__device__ __forceinline__ void ldsm_x4t(uint32_t* r, uint32_t addr) {
    asm volatile("ldmatrix.sync.aligned.m8n8.x4.trans.shared.b16 {%0,%1,%2,%3}, [%4];"
                 : "=r"(r[0]), "=r"(r[1]), "=r"(r[2]), "=r"(r[3]) : "r"(addr));
}
__device__ __forceinline__ void mma16816(float* c, const uint32_t* a, const uint32_t* b) {
    asm volatile("mma.sync.aligned.m16n8k16.row.col.f32.f16.f16.f32 "
                 "{%0,%1,%2,%3}, {%4,%5,%6,%7}, {%8,%9}, {%0,%1,%2,%3};"
                 : "+f"(c[0]), "+f"(c[1]), "+f"(c[2]), "+f"(c[3])
                 : "r"(a[0]), "r"(a[1]), "r"(a[2]), "r"(a[3]), "r"(b[0]), "r"(b[1]));
}
#define CP_ASYNC16(dst, src) \
    asm volatile("cp.async.ca.shared.global [%0], [%1], 16;" :: "r"(dst), "l"(src))
#define CP_COMMIT()  asm volatile("cp.async.commit_group;")
#define CP_WAIT0()   asm volatile("cp.async.wait_group 0;")
#define CP_WAIT1()   asm volatile("cp.async.wait_group 1;")

// ---- Wv -> fp16 (1:1 layout) ----
__global__ void convert_b_kernel(const float* __restrict__ Wv) {
    int idx = blockIdx.x * 256 + threadIdx.x;   // 65536 total
    g_Bh[idx] = __float2half_rn(Wv[idx]);
}

__global__ __launch_bounds__(256, 1) void gemm_ln_kernel(
    const float* __restrict__ x,
    const float* __restrict__ lgamma, const float* __restrict__ lbeta,
    float* __restrict__ out)
{
    extern __shared__ __align__(16) char smem[];
    const uint32_t sbB = smem_u32(smem + SM_B);
    const uint32_t sbA = smem_u32(smem + SM_A);
    const uint32_t sbS = smem_u32(smem + SM_S);

    const int tid  = threadIdx.x;
    const int lane = tid & 31;
    const int wid  = tid >> 5;
    const int ntl  = (NTILE - blockIdx.x + GRID - 1) / GRID;   // tiles for this CTA
    const int lastT = blockIdx.x + (ntl - 1) * GRID;

    // ---- B fill (all threads): 8192 x 16B cp.async ----
    for (int it = 0; it < 32; ++it) {
        int seg = tid + it * 256;
        int k  = seg >> 5;
        int ch = seg & 31;
        CP_ASYNC16(sbB + (uint32_t)(k * 512 + ((ch ^ (k & 7)) << 4)),
                   (const void*)(g_Bh + k * 256 + ch * 8));
    }
    CP_COMMIT();
    CP_WAIT0();
    __syncthreads();

    if (wid >= 4) {
        // =================== PRODUCER (warps 4-7) ===================
        const int p = tid - 128;                  // 0..127
        const int nchunks = ntl * 4;              // 16-row chunks

        auto issue = [&](int ii) {
            int tt = blockIdx.x + (ii >> 2) * GRID;
            if (tt > lastT) tt = lastT;
            const float* src = x + (size_t)tt * 16384 + (ii & 3) * 4096;
            uint32_t dst = sbS + (uint32_t)((ii & 1) * 16384);
#pragma unroll
            for (int s = 0; s < 8; ++s) {
                int slot = p + s * 128;
                CP_ASYNC16(dst + (uint32_t)(slot * 16), (const void*)(src + slot * 4));
            }
            CP_COMMIT();
        };
        issue(0);
        issue(1);

        for (int i = 0; i < nchunks; ++i) {
            const int buf = (i >> 2) & 1;
            if ((i & 3) == 0 && (i >> 2) >= 2)
                bar_sync(BAR_EMPTY0 + buf);       // consumer freed this buffer
            if (i >= nchunks - 2) { CP_WAIT0(); } else { CP_WAIT1(); }
            const char* sB = smem + SM_S + (i & 1) * 16384;
            char* aB = smem + SM_A + buf * 32768;
            const int r0 = (i & 3) * 16;
#pragma unroll
            for (int s = 0; s < 8; ++s) {
                int slot = p + s * 128;
                float4 a = *(const float4*)(sB + slot * 16);
                int row = r0 + (slot >> 6);
                int c4  = (slot & 63) << 2;
                int ch  = c4 >> 3;
                int hf  = (c4 >> 2) & 1;
                __half2 lo = __floats2half2_rn(a.x, a.y);
                __half2 hi = __floats2half2_rn(a.z, a.w);
                uint2 pk;
                pk.x = *(uint32_t*)&lo;
                pk.y = *(uint32_t*)&hi;
                *(uint2*)(aB + row * 512 + ((ch ^ (row & 7)) << 4) + hf * 8) = pk;
            }
            if ((i & 3) == 3) {
                __threadfence_block();
                bar_arrive(BAR_FULL0 + buf);      // buffer ready
            }
            int ii = i + 2;
            if (ii < nchunks) issue(ii);
        }
        CP_WAIT0();   // drain before exit
    } else {
        // =================== CONSUMER (warps 0-3) ===================
        const int head = wid;         // each warp: 64 rows x one 64-col head

        const int hi4 = lane >> 4;
        const int bt  = lane >> 3;
        const int klane = ((bt & 1) << 3) + (lane & 7);
        const int cb0   = head * 8 + (bt >> 1);
        uint32_t aRowOff[4]; int aR7[4];
#pragma unroll
        for (int mb = 0; mb < 4; ++mb) {
            int row = mb * 16 + (lane & 15);
            aRowOff[mb] = (uint32_t)(row * 512);
            aR7[mb]     = row & 7;
        }
        uint32_t bBase[4];
#pragma unroll
        for (int nb16 = 0; nb16 < 4; ++nb16) {
            int ch = cb0 + nb16 * 2;
            bBase[nb16] = sbB + (uint32_t)(klane * 512 + ((ch ^ (klane & 7)) << 4));
        }
        float g0[8], g1[8], be0[8], be1[8];
#pragma unroll
        for (int nb = 0; nb < 8; ++nb) {
            int dv = nb * 8 + (lane & 3) * 2;
            g0[nb]  = lgamma[dv];  g1[nb]  = lgamma[dv + 1];
            be0[nb] = lbeta[dv];   be1[nb] = lbeta[dv + 1];
        }

        int lt = 0;
        for (int t = blockIdx.x; t < NTILE; t += GRID, ++lt) {
            const int buf = lt & 1;
            bar_sync(BAR_FULL0 + buf);            // A[buf] ready
            const uint32_t aB = sbA + (uint32_t)(buf * 32768);

            float C[4][8][4];
#pragma unroll
            for (int mb = 0; mb < 4; ++mb)
#pragma unroll
                for (int nb = 0; nb < 8; ++nb)
#pragma unroll
                    for (int r = 0; r < 4; ++r) C[mb][nb][r] = 0.f;

#pragma unroll 2
            for (int k16 = 0; k16 < 16; ++k16) {
                uint32_t af[4][4], bf[4][4];
#pragma unroll
                for (int mb = 0; mb < 4; ++mb) {
                    int chA = k16 * 2 + hi4;
                    ldsm_x4(af[mb], aB + aRowOff[mb] + (uint32_t)((chA ^ aR7[mb]) << 4));
                }
#pragma unroll
                for (int nb16 = 0; nb16 < 4; ++nb16)
                    ldsm_x4t(bf[nb16], bBase[nb16] + (uint32_t)(k16 * 8192));
#pragma unroll
                for (int mb = 0; mb < 4; ++mb)
#pragma unroll
                    for (int nb = 0; nb < 8; ++nb)
                        mma16816(C[mb][nb], af[mb], &bf[nb >> 1][(nb & 1) * 2]);
            }
            bar_arrive(BAR_EMPTY0 + buf);         // A[buf] free for producer

            // ---- warp-local LayerNorm + permuted store ----
            const int m0 = t * 64;
#pragma unroll
            for (int mb = 0; mb < 4; ++mb)
#pragma unroll
                for (int half = 0; half < 2; ++half) {
                    float s = 0.f, q = 0.f;
#pragma unroll
                    for (int nb = 0; nb < 8; ++nb) {
                        float v0 = C[mb][nb][2 * half];
                        float v1 = C[mb][nb][2 * half + 1];
                        s += v0 + v1;
                        q += v0 * v0 + v1 * v1;
                    }
                    s += __shfl_xor_sync(0xffffffffu, s, 1);
                    q += __shfl_xor_sync(0xffffffffu, q, 1);
                    s += __shfl_xor_sync(0xffffffffu, s, 2);
                    q += __shfl_xor_sync(0xffffffffu, q, 2);
                    const float mu   = s * (1.0f / 64.0f);
                    const float var  = q * (1.0f / 64.0f) - mu * mu;
                    const float rstd = rsqrtf(fmaxf(var, 0.f) + 1e-30f);

                    const int m    = m0 + mb * 16 + half * 8 + (lane >> 2);
                    const int orow = (m & 15) * Nn + (m >> 4);
                    float* obase = out + (size_t)orow * 256 + head * 64;
#pragma unroll
                    for (int nb = 0; nb < 8; ++nb) {
                        int c = nb * 8 + (lane & 3) * 2;
                        float2 o;
                        o.x = (C[mb][nb][2 * half]     - mu) * rstd * g0[nb] + be0[nb];
                        o.y = (C[mb][nb][2 * half + 1] - mu) * rstd * g1[nb] + be1[nb];
                        __stcs((float2*)(obase + c), o);
                    }
                }
        }
    }
}

// ======================= launch =============================================
extern "C" void kernel_launch(void* const* d_in, const int* in_sizes, int n_in,
                              void* d_out, int out_size)
{
    const float* x  = (const float*)d_in[0];
    const float* Wv = (const float*)d_in[4];
    const float* lg = (const float*)d_in[5];
    const float* lb = (const float*)d_in[6];
    float* out = (float*)d_out;
    (void)in_sizes; (void)n_in; (void)out_size;

    cudaFuncSetAttribute(gemm_ln_kernel,
                         cudaFuncAttributeMaxDynamicSharedMemorySize, SM_TOT);

    convert_b_kernel<<<256, 256>>>(Wv);
    gemm_ln_kernel<<<GRID, 256, SM_TOT>>>(x, lg, lb, out);
}